// round 3
// baseline (speedup 1.0000x reference)
#include <cuda_runtime.h>
#include <cstdint>

#define TOK_N 131072   // B*T = 64*2048
#define DD    256      // D = V = 256
#define TT    2048

constexpr int BM = 64, BN = 64, BK = 32;

// Scratch (device globals: allocation-free rule)
__device__ float g_wx  [TOK_N * DD];   // 128 MB
__device__ float g_gate[TOK_N * DD];   // 128 MB
__device__ float g_ys  [TOK_N * DD];   // 128 MB

// ---------------------------------------------------------------------------
// Kernel 1: fused embed-gather + dual projection
//   g_wx[m][e]   = sum_d E[tok[m]][d] * Wx[e][d]
//   g_gate[m][e] = sigmoid( sum_d E[tok[m]][d] * Wz[e][d] )
// NT GEMM: both operands are k-contiguous.
// ---------------------------------------------------------------------------
__global__ __launch_bounds__(256) void proj_kernel(
    const int*   __restrict__ tokens,
    const float* __restrict__ E,
    const float* __restrict__ Wx,
    const float* __restrict__ Wz)
{
    __shared__ float As[BK][BM + 4];
    __shared__ float Bx[BK][BN + 4];
    __shared__ float Bz[BK][BN + 4];

    const int tid = threadIdx.x;
    const int m0  = blockIdx.x * BM;
    const int n0  = blockIdx.y * BN;

    const int lrow = tid >> 3;   // 0..31
    const int lk4  = tid & 7;    // 0..7  (float4 index along k)

    const int tok0 = tokens[m0 + lrow];
    const int tok1 = tokens[m0 + lrow + 32];

    const int tr = (tid >> 4) << 2;   // row frag 0..60
    const int tc = (tid & 15) << 2;   // col frag 0..60

    float ax[4][4], az[4][4];
#pragma unroll
    for (int i = 0; i < 4; i++)
#pragma unroll
        for (int j = 0; j < 4; j++) { ax[i][j] = 0.f; az[i][j] = 0.f; }

    for (int k0 = 0; k0 < DD; k0 += BK) {
        float4 va0  = *(const float4*)&E [tok0 * DD        + k0 + lk4 * 4];
        float4 va1  = *(const float4*)&E [tok1 * DD        + k0 + lk4 * 4];
        float4 vbx0 = *(const float4*)&Wx[(n0 + lrow)      * DD + k0 + lk4 * 4];
        float4 vbx1 = *(const float4*)&Wx[(n0 + lrow + 32) * DD + k0 + lk4 * 4];
        float4 vbz0 = *(const float4*)&Wz[(n0 + lrow)      * DD + k0 + lk4 * 4];
        float4 vbz1 = *(const float4*)&Wz[(n0 + lrow + 32) * DD + k0 + lk4 * 4];

        __syncthreads();   // protect smem from previous iteration's readers

        As[lk4*4+0][lrow]      = va0.x;  As[lk4*4+1][lrow]      = va0.y;
        As[lk4*4+2][lrow]      = va0.z;  As[lk4*4+3][lrow]      = va0.w;
        As[lk4*4+0][lrow + 32] = va1.x;  As[lk4*4+1][lrow + 32] = va1.y;
        As[lk4*4+2][lrow + 32] = va1.z;  As[lk4*4+3][lrow + 32] = va1.w;

        Bx[lk4*4+0][lrow]      = vbx0.x; Bx[lk4*4+1][lrow]      = vbx0.y;
        Bx[lk4*4+2][lrow]      = vbx0.z; Bx[lk4*4+3][lrow]      = vbx0.w;
        Bx[lk4*4+0][lrow + 32] = vbx1.x; Bx[lk4*4+1][lrow + 32] = vbx1.y;
        Bx[lk4*4+2][lrow + 32] = vbx1.z; Bx[lk4*4+3][lrow + 32] = vbx1.w;

        Bz[lk4*4+0][lrow]      = vbz0.x; Bz[lk4*4+1][lrow]      = vbz0.y;
        Bz[lk4*4+2][lrow]      = vbz0.z; Bz[lk4*4+3][lrow]      = vbz0.w;
        Bz[lk4*4+0][lrow + 32] = vbz1.x; Bz[lk4*4+1][lrow + 32] = vbz1.y;
        Bz[lk4*4+2][lrow + 32] = vbz1.z; Bz[lk4*4+3][lrow + 32] = vbz1.w;

        __syncthreads();

#pragma unroll
        for (int kk = 0; kk < BK; kk++) {
            float4 a  = *(const float4*)&As[kk][tr];
            float4 bx = *(const float4*)&Bx[kk][tc];
            float4 bz = *(const float4*)&Bz[kk][tc];
            const float av[4] = {a.x, a.y, a.z, a.w};
            const float bxv[4] = {bx.x, bx.y, bx.z, bx.w};
            const float bzv[4] = {bz.x, bz.y, bz.z, bz.w};
#pragma unroll
            for (int i = 0; i < 4; i++)
#pragma unroll
                for (int j = 0; j < 4; j++) {
                    ax[i][j] = fmaf(av[i], bxv[j], ax[i][j]);
                    az[i][j] = fmaf(av[i], bzv[j], az[i][j]);
                }
        }
    }

#pragma unroll
    for (int i = 0; i < 4; i++) {
        float4 ox = make_float4(ax[i][0], ax[i][1], ax[i][2], ax[i][3]);
        *(float4*)&g_wx[(m0 + tr + i) * DD + n0 + tc] = ox;
        float4 oz;
        oz.x = 1.f / (1.f + __expf(-az[i][0]));
        oz.y = 1.f / (1.f + __expf(-az[i][1]));
        oz.z = 1.f / (1.f + __expf(-az[i][2]));
        oz.w = 1.f / (1.f + __expf(-az[i][3]));
        *(float4*)&g_gate[(m0 + tr + i) * DD + n0 + tc] = oz;
    }
}

// ---------------------------------------------------------------------------
// Kernel 2: sequential Elman recurrence.
// 2-CTA cluster per batch row. Each CTA holds 128 rows of Wh in REGISTERS
// (256 thr x 128 fp32). Thread (eL, kh): partial dot of output row eL over
// k-half kh. New h halves exchanged via DSMEM store + cluster barrier.
// ---------------------------------------------------------------------------
__device__ __forceinline__ void cluster_sync_() {
    asm volatile("barrier.cluster.arrive.aligned;" ::: "memory");
    asm volatile("barrier.cluster.wait.aligned;"   ::: "memory");
}

__global__ void __cluster_dims__(2, 1, 1) __launch_bounds__(256, 1)
rnn_kernel(const float* __restrict__ Wh)
{
    __shared__ float h_s[DD];     // full h vector (both halves)
    __shared__ float part[128];   // cross-k-half partials

    const int tid  = threadIdx.x;
    const int b    = blockIdx.x >> 1;
    const int half = blockIdx.x & 1;     // cluster rank
    const int eL   = tid & 127;          // local output row
    const int kh   = tid >> 7;           // k-half owned by this thread
    const int eg   = half * 128 + eL;    // global output row
    const int d0   = kh * 128;

    // Load my 128 weights into registers: Wh[eg][d0 .. d0+127]
    float w[128];
#pragma unroll
    for (int i = 0; i < 128; i++) w[i] = Wh[eg * DD + d0 + i];

    h_s[tid] = 0.f;

    // peer smem address of h_s
    uint32_t h_local;
    asm("{ .reg .u64 t; cvta.to.shared.u64 t, %1; cvt.u32.u64 %0, t; }"
        : "=r"(h_local) : "l"((const void*)h_s));
    uint32_t h_peer;
    asm("mapa.shared::cluster.u32 %0, %1, %2;"
        : "=r"(h_peer) : "r"(h_local), "r"(half ^ 1));

    cluster_sync_();   // both CTAs' h_s zero-init visible cluster-wide

    const float* wx_row = g_wx   + (size_t)b * TT * DD;
    const float* gt_row = g_gate + (size_t)b * TT * DD;
    float*       y_row  = g_ys   + (size_t)b * TT * DD;

    float wx_n = 0.f, gt_n = 0.f;
    if (kh == 0) { wx_n = wx_row[eg]; gt_n = gt_row[eg]; }

    for (int t = 0; t < TT; t++) {
        const float wx_c = wx_n, gt_c = gt_n;
        if (kh == 0 && t + 1 < TT) {     // prefetch next step's inputs
            wx_n = wx_row[(t + 1) * DD + eg];
            gt_n = gt_row[(t + 1) * DD + eg];
        }

        // partial = sum over my k-half (h reads are warp-broadcast)
        float a0 = 0.f, a1 = 0.f, a2 = 0.f, a3 = 0.f;
        const float4* h4 = (const float4*)(h_s + d0);
#pragma unroll
        for (int j = 0; j < 32; j++) {
            float4 hv = h4[j];
            a0 = fmaf(w[4*j+0], hv.x, a0);
            a1 = fmaf(w[4*j+1], hv.y, a1);
            a2 = fmaf(w[4*j+2], hv.z, a2);
            a3 = fmaf(w[4*j+3], hv.w, a3);
        }
        const float acc = (a0 + a1) + (a2 + a3);

        if (kh) part[eL] = acc;
        __syncthreads();

        if (!kh) {
            const float s  = acc + part[eL];
            const float hn = tanhf(wx_c + s);
            y_row[t * DD + eg] = hn * gt_c;
            h_s[eg] = hn;   // local copy
            asm volatile("st.shared::cluster.f32 [%0], %1;"
                         :: "r"(h_peer + (uint32_t)eg * 4), "f"(hn) : "memory");
        }
        cluster_sync_();   // release my h half, acquire peer's
    }
}

// ---------------------------------------------------------------------------
// Kernel 3: tied head  out[m][v] = sum_d ys[m][d] * E[v][d]
// ---------------------------------------------------------------------------
__global__ __launch_bounds__(256) void head_kernel(
    const float* __restrict__ E, float* __restrict__ out)
{
    __shared__ float As[BK][BM + 4];
    __shared__ float Bs[BK][BN + 4];

    const int tid = threadIdx.x;
    const int m0  = blockIdx.x * BM;
    const int n0  = blockIdx.y * BN;

    const int lrow = tid >> 3;
    const int lk4  = tid & 7;
    const int tr = (tid >> 4) << 2;
    const int tc = (tid & 15) << 2;

    float acc[4][4];
#pragma unroll
    for (int i = 0; i < 4; i++)
#pragma unroll
        for (int j = 0; j < 4; j++) acc[i][j] = 0.f;

    for (int k0 = 0; k0 < DD; k0 += BK) {
        float4 va0 = *(const float4*)&g_ys[(size_t)(m0 + lrow)      * DD + k0 + lk4 * 4];
        float4 va1 = *(const float4*)&g_ys[(size_t)(m0 + lrow + 32) * DD + k0 + lk4 * 4];
        float4 vb0 = *(const float4*)&E  [(n0 + lrow)      * DD + k0 + lk4 * 4];
        float4 vb1 = *(const float4*)&E  [(n0 + lrow + 32) * DD + k0 + lk4 * 4];

        __syncthreads();

        As[lk4*4+0][lrow]      = va0.x; As[lk4*4+1][lrow]      = va0.y;
        As[lk4*4+2][lrow]      = va0.z; As[lk4*4+3][lrow]      = va0.w;
        As[lk4*4+0][lrow + 32] = va1.x; As[lk4*4+1][lrow + 32] = va1.y;
        As[lk4*4+2][lrow + 32] = va1.z; As[lk4*4+3][lrow + 32] = va1.w;

        Bs[lk4*4+0][lrow]      = vb0.x; Bs[lk4*4+1][lrow]      = vb0.y;
        Bs[lk4*4+2][lrow]      = vb0.z; Bs[lk4*4+3][lrow]      = vb0.w;
        Bs[lk4*4+0][lrow + 32] = vb1.x; Bs[lk4*4+1][lrow + 32] = vb1.y;
        Bs[lk4*4+2][lrow + 32] = vb1.z; Bs[lk4*4+3][lrow + 32] = vb1.w;

        __syncthreads();

#pragma unroll
        for (int kk = 0; kk < BK; kk++) {
            float4 a = *(const float4*)&As[kk][tr];
            float4 bv = *(const float4*)&Bs[kk][tc];
            const float av[4] = {a.x, a.y, a.z, a.w};
            const float bb[4] = {bv.x, bv.y, bv.z, bv.w};
#pragma unroll
            for (int i = 0; i < 4; i++)
#pragma unroll
                for (int j = 0; j < 4; j++)
                    acc[i][j] = fmaf(av[i], bb[j], acc[i][j]);
        }
    }

#pragma unroll
    for (int i = 0; i < 4; i++) {
        float4 o = make_float4(acc[i][0], acc[i][1], acc[i][2], acc[i][3]);
        *(float4*)&out[(size_t)(m0 + tr + i) * DD + n0 + tc] = o;
    }
}

// ---------------------------------------------------------------------------
extern "C" void kernel_launch(void* const* d_in, const int* in_sizes, int n_in,
                              void* d_out, int out_size)
{
    const int*   tokens = (const int*)  d_in[0];
    const float* E      = (const float*)d_in[1];
    const float* Wx     = (const float*)d_in[2];
    const float* Wh     = (const float*)d_in[3];
    const float* Wz     = (const float*)d_in[4];
    float* out = (float*)d_out;

    dim3 gg(TOK_N / BM, DD / BN);
    proj_kernel<<<gg, 256>>>(tokens, E, Wx, Wz);
    rnn_kernel<<<128, 256>>>(Wh);
    head_kernel<<<gg, 256>>>(E, out);
}